// round 14
// baseline (speedup 1.0000x reference)
#include <cuda_runtime.h>
#include <cuda_bf16.h>
#include <cstdint>

#define S_Q   8192
#define T_K   8192
#define CDIM  768
#define DK    128
#define DV    64
#define KSPLIT 2
#define BM    128
#define BN    128
#define QPITCH 136              // 128 + 8 halves pad -> conflict-free ldmatrix
#define NKB   (T_K / KSPLIT / BN)   // 32 key blocks per CTA
#define ATTN_SMEM 106496        // (128*136*3)*2 + (2*128 + 2*128)*4

// ---------------- scratch (no cudaMalloc allowed) ----------------
__device__ __nv_bfloat16 g_Q[S_Q * DK];
__device__ __nv_bfloat16 g_K[T_K * DK];
__device__ float g_vw[T_K];
__device__ float g_wc[CDIM];
__device__ float g_pnum[KSPLIT * S_Q];
__device__ float g_pden[KSPLIT * S_Q];
__device__ float g_sumx2;

// ---------------- PTX helpers ----------------
__device__ __forceinline__ void ldsm4(unsigned* r, uint32_t a) {
    asm volatile("ldmatrix.sync.aligned.m8n8.x4.shared.b16 {%0,%1,%2,%3}, [%4];"
                 : "=r"(r[0]), "=r"(r[1]), "=r"(r[2]), "=r"(r[3]) : "r"(a));
}
__device__ __forceinline__ void mma_bf16(float* c, const unsigned* a, const unsigned* b) {
    asm volatile("mma.sync.aligned.m16n8k16.row.col.f32.bf16.bf16.f32 "
                 "{%0,%1,%2,%3}, {%4,%5,%6,%7}, {%8,%9}, {%0,%1,%2,%3};"
                 : "+f"(c[0]), "+f"(c[1]), "+f"(c[2]), "+f"(c[3])
                 : "r"(a[0]), "r"(a[1]), "r"(a[2]), "r"(a[3]), "r"(b[0]), "r"(b[1]));
}
__device__ __forceinline__ void cp16(uint32_t s, const void* g) {
    asm volatile("cp.async.cg.shared.global [%0], [%1], 16;" :: "r"(s), "l"(g));
}
__device__ __forceinline__ float ex2f(float x) {
    float y; asm("ex2.approx.f32 %0, %1;" : "=f"(y) : "f"(x)); return y;
}

// ---------------- 1) wc = w_out @ w_v, zero sum ----------------
__global__ void prep_kernel(const float* __restrict__ w_v, const float* __restrict__ w_o) {
    int c = threadIdx.x;
    if (c == 0) g_sumx2 = 0.f;
    float acc = 0.f;
#pragma unroll 8
    for (int dv = 0; dv < DV; dv++) acc += w_o[dv] * w_v[dv * CDIM + c];
    g_wc[c] = acc;
}

// ---------------- 2) vw[t] = x2[t] . wc, plus sum(x2) ----------------
__global__ void __launch_bounds__(256) vw_kernel(const float* __restrict__ x2) {
    __shared__ float wcs[CDIM];
    int tid = threadIdx.x;
    for (int i = tid; i < CDIM; i += 256) wcs[i] = g_wc[i];
    __syncthreads();
    int warp = tid >> 5, lane = tid & 31;
    int row = blockIdx.x * 8 + warp;
    const float* xr = x2 + (size_t)row * CDIM;
    float acc = 0.f, sm = 0.f;
#pragma unroll 6
    for (int j = lane; j < CDIM; j += 32) { float v = xr[j]; acc += v * wcs[j]; sm += v; }
#pragma unroll
    for (int o = 16; o; o >>= 1) {
        acc += __shfl_xor_sync(0xffffffffu, acc, o);
        sm  += __shfl_xor_sync(0xffffffffu, sm, o);
    }
    if (lane == 0) { g_vw[row] = acc; atomicAdd(&g_sumx2, sm); }
}

// ---------------- 3) projection GEMM: C[8192,128](bf16) = A[8192,768] @ W[128,768]^T ----------------
__global__ void __launch_bounds__(256) proj_kernel(const float* __restrict__ A,
                                                   const float* __restrict__ W,
                                                   int which) {
    __shared__ alignas(16) __nv_bfloat16 As[128 * 40];
    __shared__ alignas(16) __nv_bfloat16 Ws[128 * 40];
    __nv_bfloat16* C = which ? g_K : g_Q;

    int tid = threadIdx.x, lane = tid & 31, wid = tid >> 5;
    int pm = wid >> 2, pn = wid & 3;           // warps 2(M) x 4(N), warp tile 64x32
    int mbase = blockIdx.x * 128;

    float acc[4][4][4];
#pragma unroll
    for (int i = 0; i < 4; i++)
#pragma unroll
        for (int j = 0; j < 4; j++)
#pragma unroll
            for (int k = 0; k < 4; k++) acc[i][j][k] = 0.f;

    uint32_t as_u = (uint32_t)__cvta_generic_to_shared(As);
    uint32_t ws_u = (uint32_t)__cvta_generic_to_shared(Ws);

    int lr = tid >> 1;               // 0..127
    int lc = (tid & 1) * 16;         // 0 or 16

    for (int k0 = 0; k0 < CDIM; k0 += 32) {
        const float4* ga = (const float4*)(A + (size_t)(mbase + lr) * CDIM + k0 + lc);
        const float4* gw = (const float4*)(W + (size_t)lr * CDIM + k0 + lc);
        float4 av[4], wv[4];
#pragma unroll
        for (int i = 0; i < 4; i++) { av[i] = ga[i]; wv[i] = gw[i]; }
        __syncthreads();                       // prev compute done before overwrite
        uint2* sa = (uint2*)&As[lr * 40 + lc];
        uint2* sw = (uint2*)&Ws[lr * 40 + lc];
#pragma unroll
        for (int i = 0; i < 4; i++) {
            __nv_bfloat162 p0 = __floats2bfloat162_rn(av[i].x, av[i].y);
            __nv_bfloat162 p1 = __floats2bfloat162_rn(av[i].z, av[i].w);
            sa[i] = make_uint2(*(unsigned*)&p0, *(unsigned*)&p1);
            __nv_bfloat162 q0 = __floats2bfloat162_rn(wv[i].x, wv[i].y);
            __nv_bfloat162 q1 = __floats2bfloat162_rn(wv[i].z, wv[i].w);
            sw[i] = make_uint2(*(unsigned*)&q0, *(unsigned*)&q1);
        }
        __syncthreads();
#pragma unroll
        for (int kk = 0; kk < 2; kk++) {
            unsigned af[4][4], bf2[4][2];
#pragma unroll
            for (int mt = 0; mt < 4; mt++)
                ldsm4(af[mt], as_u + (uint32_t)(((pm * 64 + mt * 16 + (lane & 15)) * 40 +
                                                 kk * 16 + (lane >> 4) * 8) * 2));
#pragma unroll
            for (int np = 0; np < 2; np++) {
                unsigned r4[4];
                ldsm4(r4, ws_u + (uint32_t)(((pn * 32 + np * 16 + (lane & 15)) * 40 +
                                             kk * 16 + (lane >> 4) * 8) * 2));
                bf2[np * 2][0] = r4[0]; bf2[np * 2][1] = r4[2];
                bf2[np * 2 + 1][0] = r4[1]; bf2[np * 2 + 1][1] = r4[3];
            }
#pragma unroll
            for (int mt = 0; mt < 4; mt++)
#pragma unroll
                for (int nt = 0; nt < 4; nt++)
                    mma_bf16(acc[mt][nt], af[mt], bf2[nt]);
        }
    }
#pragma unroll
    for (int mt = 0; mt < 4; mt++) {
        int r0 = mbase + pm * 64 + mt * 16 + (lane >> 2);
#pragma unroll
        for (int nt = 0; nt < 4; nt++) {
            int c0 = pn * 32 + nt * 8 + (lane & 3) * 2;
            __nv_bfloat162 v01 = __floats2bfloat162_rn(acc[mt][nt][0], acc[mt][nt][1]);
            __nv_bfloat162 v23 = __floats2bfloat162_rn(acc[mt][nt][2], acc[mt][nt][3]);
            *(__nv_bfloat162*)(&C[(size_t)r0 * DK + c0]) = v01;
            *(__nv_bfloat162*)(&C[(size_t)(r0 + 8) * DK + c0]) = v23;
        }
    }
}

// ---------------- 4) attention: num/den per query ----------------
__device__ __forceinline__ void load_kb(uint32_t ks_u, uint32_t vws_u, int tid, int buf, int krow0) {
    uint32_t kb = ks_u + (uint32_t)buf * (BN * QPITCH * 2);
#pragma unroll
    for (int p = 0; p < 8; p++) {
        int idx = p * 256 + tid;
        int r = idx >> 4, ch = idx & 15;
        cp16(kb + (uint32_t)((r * QPITCH + ch * 8) * 2),
             g_K + (size_t)(krow0 + r) * DK + ch * 8);
    }
    if (tid < 32)
        cp16(vws_u + (uint32_t)buf * BN * 4 + tid * 16, g_vw + krow0 + tid * 4);
}

extern __shared__ char smem_raw[];

__global__ void __launch_bounds__(256, 1) attn_kernel() {
    __nv_bfloat16* Qs = (__nv_bfloat16*)smem_raw;
    __nv_bfloat16* Ks = Qs + BM * QPITCH;
    float* vws   = (float*)(Ks + 2 * BN * QPITCH);
    float* num_s = vws + 2 * BN;
    float* den_s = num_s + BM;

    int tid = threadIdx.x, lane = tid & 31, wid = tid >> 5;
    int wm = wid >> 1, wn = wid & 1;            // warps 4(M) x 2(N), warp tile 32x64
    int qbase = blockIdx.x * BM;
    int split = blockIdx.y;
    int koff0 = split * (T_K / KSPLIT);

    uint32_t qs_u  = (uint32_t)__cvta_generic_to_shared(Qs);
    uint32_t ks_u  = (uint32_t)__cvta_generic_to_shared(Ks);
    uint32_t vws_u = (uint32_t)__cvta_generic_to_shared(vws);

#pragma unroll
    for (int p = 0; p < 8; p++) {               // Q tile, once
        int idx = p * 256 + tid;
        int r = idx >> 4, ch = idx & 15;
        cp16(qs_u + (uint32_t)((r * QPITCH + ch * 8) * 2),
             g_Q + (size_t)(qbase + r) * DK + ch * 8);
    }
    load_kb(ks_u, vws_u, tid, 0, koff0);
    asm volatile("cp.async.commit_group;");

    float acc[2][8][4];
#pragma unroll
    for (int ti = 0; ti < 2; ti++)
#pragma unroll
        for (int tj = 0; tj < 8; tj++)
#pragma unroll
            for (int q = 0; q < 4; q++) acc[ti][tj][q] = 0.f;
    float num[2][2] = {{0.f, 0.f}, {0.f, 0.f}};
    float den[2][2] = {{0.f, 0.f}, {0.f, 0.f}};

    for (int kb = 0; kb < NKB; kb++) {
        if (kb + 1 < NKB) {
            load_kb(ks_u, vws_u, tid, (kb + 1) & 1, koff0 + (kb + 1) * BN);
            asm volatile("cp.async.commit_group;");
            asm volatile("cp.async.wait_group 1;");
        } else {
            asm volatile("cp.async.wait_group 0;");
        }
        __syncthreads();
        uint32_t kbuf = ks_u + (uint32_t)(kb & 1) * (BN * QPITCH * 2);
#pragma unroll
        for (int kk = 0; kk < 8; kk++) {
            unsigned af[2][4];
#pragma unroll
            for (int ti = 0; ti < 2; ti++)
                ldsm4(af[ti], qs_u + (uint32_t)(((wm * 32 + ti * 16 + (lane & 15)) * QPITCH +
                                                 kk * 16 + (lane >> 4) * 8) * 2));
            unsigned bf2[8][2];
#pragma unroll
            for (int tp = 0; tp < 4; tp++) {
                unsigned r4[4];
                ldsm4(r4, kbuf + (uint32_t)(((wn * 64 + tp * 16 + (lane & 15)) * QPITCH +
                                             kk * 16 + (lane >> 4) * 8) * 2));
                bf2[tp * 2][0] = r4[0]; bf2[tp * 2][1] = r4[2];
                bf2[tp * 2 + 1][0] = r4[1]; bf2[tp * 2 + 1][1] = r4[3];
            }
#pragma unroll
            for (int ti = 0; ti < 2; ti++)
#pragma unroll
                for (int tj = 0; tj < 8; tj++)
                    mma_bf16(acc[ti][tj], af[ti], bf2[tj]);
        }
        // exp + weighted accumulate in registers (scores are tiny -> no max needed)
        const float SC = 0.088388347648318447f * 1.44269504088896341f; // log2(e)/sqrt(128)
        const float* vb = vws + (kb & 1) * BN;
#pragma unroll
        for (int tj = 0; tj < 8; tj++) {
            int c0 = wn * 64 + tj * 8 + (lane & 3) * 2;
            float v0 = vb[c0], v1 = vb[c0 + 1];
#pragma unroll
            for (int ti = 0; ti < 2; ti++) {
                float e0 = ex2f(acc[ti][tj][0] * SC);
                float e1 = ex2f(acc[ti][tj][1] * SC);
                float e2 = ex2f(acc[ti][tj][2] * SC);
                float e3 = ex2f(acc[ti][tj][3] * SC);
                num[ti][0] += e0 * v0 + e1 * v1;
                den[ti][0] += e0 + e1;
                num[ti][1] += e2 * v0 + e3 * v1;
                den[ti][1] += e2 + e3;
                acc[ti][tj][0] = 0.f; acc[ti][tj][1] = 0.f;
                acc[ti][tj][2] = 0.f; acc[ti][tj][3] = 0.f;
            }
        }
        __syncthreads();   // all warps done with this buffer before it is refilled
    }

    // quad reduce across (lane&3): each quad covers distinct columns of same row
#pragma unroll
    for (int ti = 0; ti < 2; ti++)
#pragma unroll
        for (int h = 0; h < 2; h++) {
            num[ti][h] += __shfl_xor_sync(0xffffffffu, num[ti][h], 1);
            num[ti][h] += __shfl_xor_sync(0xffffffffu, num[ti][h], 2);
            den[ti][h] += __shfl_xor_sync(0xffffffffu, den[ti][h], 1);
            den[ti][h] += __shfl_xor_sync(0xffffffffu, den[ti][h], 2);
        }
    if ((lane & 3) == 0 && wn == 0) {
#pragma unroll
        for (int ti = 0; ti < 2; ti++)
#pragma unroll
            for (int h = 0; h < 2; h++) {
                int r = wm * 32 + ti * 16 + h * 8 + (lane >> 2);
                num_s[r] = num[ti][h]; den_s[r] = den[ti][h];
            }
    }
    __syncthreads();
    if ((lane & 3) == 0 && wn == 1) {
#pragma unroll
        for (int ti = 0; ti < 2; ti++)
#pragma unroll
            for (int h = 0; h < 2; h++) {
                int r = wm * 32 + ti * 16 + h * 8 + (lane >> 2);
                num_s[r] += num[ti][h]; den_s[r] += den[ti][h];
            }
    }
    __syncthreads();
    if (tid < BM) {
        g_pnum[split * S_Q + qbase + tid] = num_s[tid];
        g_pden[split * S_Q + qbase + tid] = den_s[tid];
    }
}

// ---------------- 5) gate: y = x1 * (1 - num/den)  (or x1 if sum(x2)==0) ----------------
__global__ void gate_kernel(const float* __restrict__ x1, float* __restrict__ y) {
    int row = blockIdx.x;
    float nu = g_pnum[row] + g_pnum[S_Q + row];
    float de = g_pden[row] + g_pden[S_Q + row];
    float out = nu / de;
    float f = (g_sumx2 == 0.0f) ? 1.0f : (1.0f - out);
    int t = threadIdx.x;  // 192 threads * float4 = 768
    const float4* xr = (const float4*)(x1 + (size_t)row * CDIM);
    float4* yr = (float4*)(y + (size_t)row * CDIM);
    float4 v = xr[t];
    v.x *= f; v.y *= f; v.z *= f; v.w *= f;
    yr[t] = v;
}

// ---------------- launch ----------------
extern "C" void kernel_launch(void* const* d_in, const int* in_sizes, int n_in,
                              void* d_out, int out_size) {
    (void)in_sizes; (void)n_in; (void)out_size;
    const float* x1  = (const float*)d_in[0];
    const float* x2  = (const float*)d_in[1];
    const float* w_q = (const float*)d_in[2];
    const float* w_k = (const float*)d_in[3];
    const float* w_v = (const float*)d_in[4];
    const float* w_o = (const float*)d_in[5];
    float* y = (float*)d_out;

    cudaFuncSetAttribute(attn_kernel, cudaFuncAttributeMaxDynamicSharedMemorySize, ATTN_SMEM);

    prep_kernel<<<1, CDIM>>>(w_v, w_o);
    vw_kernel<<<T_K / 8, 256>>>(x2);
    proj_kernel<<<S_Q / BM, 256>>>(x1, w_q, 0);
    proj_kernel<<<T_K / BM, 256>>>(x2, w_k, 1);
    attn_kernel<<<dim3(S_Q / BM, KSPLIT), 256, ATTN_SMEM>>>();
    gate_kernel<<<S_Q, CDIM / 4>>>(x1, y);
}

// round 15
// speedup vs baseline: 1.2752x; 1.2752x over previous
#include <cuda_runtime.h>
#include <cuda_bf16.h>
#include <cstdint>

#define S_Q   8192
#define T_K   8192
#define CDIM  768
#define DK    128
#define DV    64
#define KSPLIT 2
#define BM    128
#define BN    128
#define QPITCH 136              // 128 + 8 halves pad -> conflict-free ldmatrix
#define NKB   (T_K / KSPLIT / BN)   // 32 key blocks per CTA
#define ATTN_SMEM 106496        // (128*136*3)*2 + (2*128 + 2*128)*4

// ---------------- scratch (no cudaMalloc allowed) ----------------
__device__ __nv_bfloat16 g_Q[S_Q * DK];
__device__ __nv_bfloat16 g_K[T_K * DK];
__device__ float g_vw[T_K];
__device__ float g_wc[CDIM];
__device__ float g_pnum[KSPLIT * S_Q];
__device__ float g_pden[KSPLIT * S_Q];
__device__ float g_sumx2;

// ---------------- PTX helpers ----------------
__device__ __forceinline__ void ldsm4(unsigned* r, uint32_t a) {
    asm volatile("ldmatrix.sync.aligned.m8n8.x4.shared.b16 {%0,%1,%2,%3}, [%4];"
                 : "=r"(r[0]), "=r"(r[1]), "=r"(r[2]), "=r"(r[3]) : "r"(a));
}
__device__ __forceinline__ void mma_bf16(float* c, const unsigned* a, const unsigned* b) {
    asm volatile("mma.sync.aligned.m16n8k16.row.col.f32.bf16.bf16.f32 "
                 "{%0,%1,%2,%3}, {%4,%5,%6,%7}, {%8,%9}, {%0,%1,%2,%3};"
                 : "+f"(c[0]), "+f"(c[1]), "+f"(c[2]), "+f"(c[3])
                 : "r"(a[0]), "r"(a[1]), "r"(a[2]), "r"(a[3]), "r"(b[0]), "r"(b[1]));
}
__device__ __forceinline__ void cp16(uint32_t s, const void* g) {
    asm volatile("cp.async.cg.shared.global [%0], [%1], 16;" :: "r"(s), "l"(g));
}
__device__ __forceinline__ float ex2f(float x) {
    float y; asm("ex2.approx.f32 %0, %1;" : "=f"(y) : "f"(x)); return y;
}

// ---------------- 1) wc = w_out @ w_v, zero sum ----------------
__global__ void prep_kernel(const float* __restrict__ w_v, const float* __restrict__ w_o) {
    int c = threadIdx.x;
    if (c == 0) g_sumx2 = 0.f;
    float acc = 0.f;
#pragma unroll 8
    for (int dv = 0; dv < DV; dv++) acc += w_o[dv] * w_v[dv * CDIM + c];
    g_wc[c] = acc;
}

// ---------------- 2) vw[t] = x2[t] . wc, plus sum(x2) ----------------
__global__ void __launch_bounds__(256) vw_kernel(const float* __restrict__ x2) {
    __shared__ float wcs[CDIM];
    int tid = threadIdx.x;
    for (int i = tid; i < CDIM; i += 256) wcs[i] = g_wc[i];
    __syncthreads();
    int warp = tid >> 5, lane = tid & 31;
    int row = blockIdx.x * 8 + warp;
    const float* xr = x2 + (size_t)row * CDIM;
    float acc = 0.f, sm = 0.f;
#pragma unroll 6
    for (int j = lane; j < CDIM; j += 32) { float v = xr[j]; acc += v * wcs[j]; sm += v; }
#pragma unroll
    for (int o = 16; o; o >>= 1) {
        acc += __shfl_xor_sync(0xffffffffu, acc, o);
        sm  += __shfl_xor_sync(0xffffffffu, sm, o);
    }
    if (lane == 0) { g_vw[row] = acc; atomicAdd(&g_sumx2, sm); }
}

// ---------------- 3) FUSED projection GEMMs (Q and K in one wave) ----------------
// C[8192,128](bf16) = A[8192,768] @ W[128,768]^T ;  blockIdx.y selects {Q, K}.
// Register-prefetch pipeline: LDGs for iter k+1 issued before the MMA block of
// iter k, hiding L2/DRAM latency behind ldsm+mma.
__global__ void __launch_bounds__(256) proj2_kernel(const float* __restrict__ Aq,
                                                    const float* __restrict__ Ak,
                                                    const float* __restrict__ Wq,
                                                    const float* __restrict__ Wk) {
    __shared__ alignas(16) __nv_bfloat16 As[128 * 40];
    __shared__ alignas(16) __nv_bfloat16 Ws[128 * 40];
    int which = blockIdx.y;
    const float* __restrict__ A = which ? Ak : Aq;
    const float* __restrict__ W = which ? Wk : Wq;
    __nv_bfloat16* C = which ? g_K : g_Q;

    int tid = threadIdx.x, lane = tid & 31, wid = tid >> 5;
    int pm = wid >> 2, pn = wid & 3;           // warps 2(M) x 4(N), warp tile 64x32
    int mbase = blockIdx.x * 128;

    float acc[4][4][4];
#pragma unroll
    for (int i = 0; i < 4; i++)
#pragma unroll
        for (int j = 0; j < 4; j++)
#pragma unroll
            for (int k = 0; k < 4; k++) acc[i][j][k] = 0.f;

    uint32_t as_u = (uint32_t)__cvta_generic_to_shared(As);
    uint32_t ws_u = (uint32_t)__cvta_generic_to_shared(Ws);

    int lr = tid >> 1;               // 0..127
    int lc = (tid & 1) * 16;         // 0 or 16

    const float* ga_base = A + (size_t)(mbase + lr) * CDIM + lc;
    const float* gw_base = W + (size_t)lr * CDIM + lc;

    float4 av[4], wv[4];
    // prologue: load K-chunk 0
#pragma unroll
    for (int i = 0; i < 4; i++) {
        av[i] = ((const float4*)ga_base)[i];
        wv[i] = ((const float4*)gw_base)[i];
    }

    for (int k0 = 0; k0 < CDIM; k0 += 32) {
        if (k0) __syncthreads();               // prev compute done before overwrite
        uint2* sa = (uint2*)&As[lr * 40 + lc];
        uint2* sw = (uint2*)&Ws[lr * 40 + lc];
#pragma unroll
        for (int i = 0; i < 4; i++) {
            __nv_bfloat162 p0 = __floats2bfloat162_rn(av[i].x, av[i].y);
            __nv_bfloat162 p1 = __floats2bfloat162_rn(av[i].z, av[i].w);
            sa[i] = make_uint2(*(unsigned*)&p0, *(unsigned*)&p1);
            __nv_bfloat162 q0 = __floats2bfloat162_rn(wv[i].x, wv[i].y);
            __nv_bfloat162 q1 = __floats2bfloat162_rn(wv[i].z, wv[i].w);
            sw[i] = make_uint2(*(unsigned*)&q0, *(unsigned*)&q1);
        }
        __syncthreads();
        // prefetch next K-chunk while this one is consumed by ldsm/mma
        if (k0 + 32 < CDIM) {
            const float4* ga = (const float4*)(ga_base + k0 + 32);
            const float4* gw = (const float4*)(gw_base + k0 + 32);
#pragma unroll
            for (int i = 0; i < 4; i++) { av[i] = ga[i]; wv[i] = gw[i]; }
        }
#pragma unroll
        for (int kk = 0; kk < 2; kk++) {
            unsigned af[4][4], bf2[4][2];
#pragma unroll
            for (int mt = 0; mt < 4; mt++)
                ldsm4(af[mt], as_u + (uint32_t)(((pm * 64 + mt * 16 + (lane & 15)) * 40 +
                                                 kk * 16 + (lane >> 4) * 8) * 2));
#pragma unroll
            for (int np = 0; np < 2; np++) {
                unsigned r4[4];
                ldsm4(r4, ws_u + (uint32_t)(((pn * 32 + np * 16 + (lane & 15)) * 40 +
                                             kk * 16 + (lane >> 4) * 8) * 2));
                bf2[np * 2][0] = r4[0]; bf2[np * 2][1] = r4[2];
                bf2[np * 2 + 1][0] = r4[1]; bf2[np * 2 + 1][1] = r4[3];
            }
#pragma unroll
            for (int mt = 0; mt < 4; mt++)
#pragma unroll
                for (int nt = 0; nt < 4; nt++)
                    mma_bf16(acc[mt][nt], af[mt], bf2[nt]);
        }
    }
#pragma unroll
    for (int mt = 0; mt < 4; mt++) {
        int r0 = mbase + pm * 64 + mt * 16 + (lane >> 2);
#pragma unroll
        for (int nt = 0; nt < 4; nt++) {
            int c0 = pn * 32 + nt * 8 + (lane & 3) * 2;
            __nv_bfloat162 v01 = __floats2bfloat162_rn(acc[mt][nt][0], acc[mt][nt][1]);
            __nv_bfloat162 v23 = __floats2bfloat162_rn(acc[mt][nt][2], acc[mt][nt][3]);
            *(__nv_bfloat162*)(&C[(size_t)r0 * DK + c0]) = v01;
            *(__nv_bfloat162*)(&C[(size_t)(r0 + 8) * DK + c0]) = v23;
        }
    }
}

// ---------------- 4) attention: num/den per query ----------------
__device__ __forceinline__ void load_kb(uint32_t ks_u, uint32_t vws_u, int tid, int buf, int krow0) {
    uint32_t kb = ks_u + (uint32_t)buf * (BN * QPITCH * 2);
#pragma unroll
    for (int p = 0; p < 8; p++) {
        int idx = p * 256 + tid;
        int r = idx >> 4, ch = idx & 15;
        cp16(kb + (uint32_t)((r * QPITCH + ch * 8) * 2),
             g_K + (size_t)(krow0 + r) * DK + ch * 8);
    }
    if (tid < 32)
        cp16(vws_u + (uint32_t)buf * BN * 4 + tid * 16, g_vw + krow0 + tid * 4);
}

extern __shared__ char smem_raw[];

__global__ void __launch_bounds__(256, 1) attn_kernel() {
    __nv_bfloat16* Qs = (__nv_bfloat16*)smem_raw;
    __nv_bfloat16* Ks = Qs + BM * QPITCH;
    float* vws   = (float*)(Ks + 2 * BN * QPITCH);
    float* num_s = vws + 2 * BN;
    float* den_s = num_s + BM;

    int tid = threadIdx.x, lane = tid & 31, wid = tid >> 5;
    int wm = wid >> 1, wn = wid & 1;            // warps 4(M) x 2(N), warp tile 32x64
    int qbase = blockIdx.x * BM;
    int split = blockIdx.y;
    int koff0 = split * (T_K / KSPLIT);

    uint32_t qs_u  = (uint32_t)__cvta_generic_to_shared(Qs);
    uint32_t ks_u  = (uint32_t)__cvta_generic_to_shared(Ks);
    uint32_t vws_u = (uint32_t)__cvta_generic_to_shared(vws);

#pragma unroll
    for (int p = 0; p < 8; p++) {               // Q tile, once
        int idx = p * 256 + tid;
        int r = idx >> 4, ch = idx & 15;
        cp16(qs_u + (uint32_t)((r * QPITCH + ch * 8) * 2),
             g_Q + (size_t)(qbase + r) * DK + ch * 8);
    }
    load_kb(ks_u, vws_u, tid, 0, koff0);
    asm volatile("cp.async.commit_group;");

    float acc[2][8][4];
#pragma unroll
    for (int ti = 0; ti < 2; ti++)
#pragma unroll
        for (int tj = 0; tj < 8; tj++)
#pragma unroll
            for (int q = 0; q < 4; q++) acc[ti][tj][q] = 0.f;
    float num[2][2] = {{0.f, 0.f}, {0.f, 0.f}};
    float den[2][2] = {{0.f, 0.f}, {0.f, 0.f}};

    for (int kb = 0; kb < NKB; kb++) {
        if (kb + 1 < NKB) {
            load_kb(ks_u, vws_u, tid, (kb + 1) & 1, koff0 + (kb + 1) * BN);
            asm volatile("cp.async.commit_group;");
            asm volatile("cp.async.wait_group 1;");
        } else {
            asm volatile("cp.async.wait_group 0;");
        }
        __syncthreads();
        uint32_t kbuf = ks_u + (uint32_t)(kb & 1) * (BN * QPITCH * 2);
#pragma unroll
        for (int kk = 0; kk < 8; kk++) {
            unsigned af[2][4];
#pragma unroll
            for (int ti = 0; ti < 2; ti++)
                ldsm4(af[ti], qs_u + (uint32_t)(((wm * 32 + ti * 16 + (lane & 15)) * QPITCH +
                                                 kk * 16 + (lane >> 4) * 8) * 2));
            unsigned bf2[8][2];
#pragma unroll
            for (int tp = 0; tp < 4; tp++) {
                unsigned r4[4];
                ldsm4(r4, kbuf + (uint32_t)(((wn * 64 + tp * 16 + (lane & 15)) * QPITCH +
                                             kk * 16 + (lane >> 4) * 8) * 2));
                bf2[tp * 2][0] = r4[0]; bf2[tp * 2][1] = r4[2];
                bf2[tp * 2 + 1][0] = r4[1]; bf2[tp * 2 + 1][1] = r4[3];
            }
#pragma unroll
            for (int ti = 0; ti < 2; ti++)
#pragma unroll
                for (int tj = 0; tj < 8; tj++)
                    mma_bf16(acc[ti][tj], af[ti], bf2[tj]);
        }
        // exp + weighted accumulate in registers (scores are tiny -> no max needed)
        const float SC = 0.088388347648318447f * 1.44269504088896341f; // log2(e)/sqrt(128)
        const float* vb = vws + (kb & 1) * BN;
#pragma unroll
        for (int tj = 0; tj < 8; tj++) {
            int c0 = wn * 64 + tj * 8 + (lane & 3) * 2;
            float v0 = vb[c0], v1 = vb[c0 + 1];
#pragma unroll
            for (int ti = 0; ti < 2; ti++) {
                float e0 = ex2f(acc[ti][tj][0] * SC);
                float e1 = ex2f(acc[ti][tj][1] * SC);
                float e2 = ex2f(acc[ti][tj][2] * SC);
                float e3 = ex2f(acc[ti][tj][3] * SC);
                num[ti][0] += e0 * v0 + e1 * v1;
                den[ti][0] += e0 + e1;
                num[ti][1] += e2 * v0 + e3 * v1;
                den[ti][1] += e2 + e3;
                acc[ti][tj][0] = 0.f; acc[ti][tj][1] = 0.f;
                acc[ti][tj][2] = 0.f; acc[ti][tj][3] = 0.f;
            }
        }
        __syncthreads();   // all warps done with this buffer before it is refilled
    }

    // quad reduce across (lane&3): each quad covers distinct columns of same row
#pragma unroll
    for (int ti = 0; ti < 2; ti++)
#pragma unroll
        for (int h = 0; h < 2; h++) {
            num[ti][h] += __shfl_xor_sync(0xffffffffu, num[ti][h], 1);
            num[ti][h] += __shfl_xor_sync(0xffffffffu, num[ti][h], 2);
            den[ti][h] += __shfl_xor_sync(0xffffffffu, den[ti][h], 1);
            den[ti][h] += __shfl_xor_sync(0xffffffffu, den[ti][h], 2);
        }
    if ((lane & 3) == 0 && wn == 0) {
#pragma unroll
        for (int ti = 0; ti < 2; ti++)
#pragma unroll
            for (int h = 0; h < 2; h++) {
                int r = wm * 32 + ti * 16 + h * 8 + (lane >> 2);
                num_s[r] = num[ti][h]; den_s[r] = den[ti][h];
            }
    }
    __syncthreads();
    if ((lane & 3) == 0 && wn == 1) {
#pragma unroll
        for (int ti = 0; ti < 2; ti++)
#pragma unroll
            for (int h = 0; h < 2; h++) {
                int r = wm * 32 + ti * 16 + h * 8 + (lane >> 2);
                num_s[r] += num[ti][h]; den_s[r] += den[ti][h];
            }
    }
    __syncthreads();
    if (tid < BM) {
        g_pnum[split * S_Q + qbase + tid] = num_s[tid];
        g_pden[split * S_Q + qbase + tid] = den_s[tid];
    }
}

// ---------------- 5) gate: y = x1 * (1 - num/den)  (or x1 if sum(x2)==0) ----------------
__global__ void gate_kernel(const float* __restrict__ x1, float* __restrict__ y) {
    int row = blockIdx.x;
    float nu = g_pnum[row] + g_pnum[S_Q + row];
    float de = g_pden[row] + g_pden[S_Q + row];
    float out = nu / de;
    float f = (g_sumx2 == 0.0f) ? 1.0f : (1.0f - out);
    int t = threadIdx.x;  // 192 threads * float4 = 768
    const float4* xr = (const float4*)(x1 + (size_t)row * CDIM);
    float4* yr = (float4*)(y + (size_t)row * CDIM);
    float4 v = xr[t];
    v.x *= f; v.y *= f; v.z *= f; v.w *= f;
    yr[t] = v;
}

// ---------------- launch ----------------
extern "C" void kernel_launch(void* const* d_in, const int* in_sizes, int n_in,
                              void* d_out, int out_size) {
    (void)in_sizes; (void)n_in; (void)out_size;
    const float* x1  = (const float*)d_in[0];
    const float* x2  = (const float*)d_in[1];
    const float* w_q = (const float*)d_in[2];
    const float* w_k = (const float*)d_in[3];
    const float* w_v = (const float*)d_in[4];
    const float* w_o = (const float*)d_in[5];
    float* y = (float*)d_out;

    cudaFuncSetAttribute(attn_kernel, cudaFuncAttributeMaxDynamicSharedMemorySize, ATTN_SMEM);

    prep_kernel<<<1, CDIM>>>(w_v, w_o);
    vw_kernel<<<T_K / 8, 256>>>(x2);
    proj2_kernel<<<dim3(S_Q / BM, 2), 256>>>(x1, x2, w_q, w_k);
    attn_kernel<<<dim3(S_Q / BM, KSPLIT), 256, ATTN_SMEM>>>();
    gate_kernel<<<S_Q, CDIM / 4>>>(x1, y);
}

// round 16
// speedup vs baseline: 1.3928x; 1.0922x over previous
#include <cuda_runtime.h>
#include <cuda_bf16.h>
#include <cstdint>

#define S_Q   8192
#define T_K   8192
#define CDIM  768
#define DK    128
#define DV    64
#define KSPLIT 4
#define BM    128
#define BN    128
#define QPITCH 136              // 128 + 8 halves pad -> conflict-free ldmatrix
#define NKB   (T_K / KSPLIT / BN)   // 16 key blocks per CTA
#define ATTN_SMEM 106496        // (128*136*3)*2 + (2*128 + 2*128)*4
// softmax scale folded into Q: log2(e)/sqrt(128)
#define SCQ (0.088388347648318447f * 1.44269504088896341f)

// ---------------- scratch (no cudaMalloc allowed) ----------------
__device__ __nv_bfloat16 g_Q[S_Q * DK];   // pre-scaled by SCQ
__device__ __nv_bfloat16 g_K[T_K * DK];
__device__ float g_vw[T_K];
__device__ float g_wc[CDIM];
__device__ float g_pnum[KSPLIT * S_Q];
__device__ float g_pden[KSPLIT * S_Q];
__device__ float g_sumx2;

// ---------------- PTX helpers ----------------
__device__ __forceinline__ void ldsm4(unsigned* r, uint32_t a) {
    asm volatile("ldmatrix.sync.aligned.m8n8.x4.shared.b16 {%0,%1,%2,%3}, [%4];"
                 : "=r"(r[0]), "=r"(r[1]), "=r"(r[2]), "=r"(r[3]) : "r"(a));
}
__device__ __forceinline__ void mma_bf16(float* c, const unsigned* a, const unsigned* b) {
    asm volatile("mma.sync.aligned.m16n8k16.row.col.f32.bf16.bf16.f32 "
                 "{%0,%1,%2,%3}, {%4,%5,%6,%7}, {%8,%9}, {%0,%1,%2,%3};"
                 : "+f"(c[0]), "+f"(c[1]), "+f"(c[2]), "+f"(c[3])
                 : "r"(a[0]), "r"(a[1]), "r"(a[2]), "r"(a[3]), "r"(b[0]), "r"(b[1]));
}
__device__ __forceinline__ void cp16(uint32_t s, const void* g) {
    asm volatile("cp.async.cg.shared.global [%0], [%1], 16;" :: "r"(s), "l"(g));
}
__device__ __forceinline__ float ex2f(float x) {
    float y; asm("ex2.approx.f32 %0, %1;" : "=f"(y) : "f"(x)); return y;
}

// ---------------- 1) wc = w_out @ w_v, zero sum ----------------
__global__ void prep_kernel(const float* __restrict__ w_v, const float* __restrict__ w_o) {
    int c = threadIdx.x;
    if (c == 0) g_sumx2 = 0.f;
    float acc = 0.f;
#pragma unroll 8
    for (int dv = 0; dv < DV; dv++) acc += w_o[dv] * w_v[dv * CDIM + c];
    g_wc[c] = acc;
}

// ---------------- 2) vw[t] = x2[t] . wc, plus sum(x2) ----------------
__global__ void __launch_bounds__(256) vw_kernel(const float* __restrict__ x2) {
    __shared__ float wcs[CDIM];
    int tid = threadIdx.x;
    for (int i = tid; i < CDIM; i += 256) wcs[i] = g_wc[i];
    __syncthreads();
    int warp = tid >> 5, lane = tid & 31;
    int row = blockIdx.x * 8 + warp;
    const float* xr = x2 + (size_t)row * CDIM;
    float acc = 0.f, sm = 0.f;
#pragma unroll 6
    for (int j = lane; j < CDIM; j += 32) { float v = xr[j]; acc += v * wcs[j]; sm += v; }
#pragma unroll
    for (int o = 16; o; o >>= 1) {
        acc += __shfl_xor_sync(0xffffffffu, acc, o);
        sm  += __shfl_xor_sync(0xffffffffu, sm, o);
    }
    if (lane == 0) { g_vw[row] = acc; atomicAdd(&g_sumx2, sm); }
}

// ---------------- 3) FUSED projection GEMMs, BM=64, 2 CTAs/SM ----------------
// C[8192,128](bf16) = A[8192,768] @ W[128,768]^T ;  blockIdx.y selects {Q, K}.
// Q output is pre-scaled by SCQ so attention can exp2 scores directly.
__global__ void __launch_bounds__(256, 2) proj2_kernel(const float* __restrict__ Aq,
                                                       const float* __restrict__ Ak,
                                                       const float* __restrict__ Wq,
                                                       const float* __restrict__ Wk) {
    __shared__ alignas(16) __nv_bfloat16 As[64 * 40];
    __shared__ alignas(16) __nv_bfloat16 Ws[128 * 40];
    int which = blockIdx.y;
    const float* __restrict__ A = which ? Ak : Aq;
    const float* __restrict__ W = which ? Wk : Wq;
    __nv_bfloat16* C = which ? g_K : g_Q;
    float oscale = which ? 1.0f : SCQ;

    int tid = threadIdx.x, lane = tid & 31, wid = tid >> 5;
    int pm = wid >> 2, pn = wid & 3;           // warps 2(M) x 4(N), warp tile 32x32
    int mbase = blockIdx.x * 64;

    float acc[2][4][4];
#pragma unroll
    for (int i = 0; i < 2; i++)
#pragma unroll
        for (int j = 0; j < 4; j++)
#pragma unroll
            for (int k = 0; k < 4; k++) acc[i][j][k] = 0.f;

    uint32_t as_u = (uint32_t)__cvta_generic_to_shared(As);
    uint32_t ws_u = (uint32_t)__cvta_generic_to_shared(Ws);

    int lr_a = tid >> 2;               // 0..63
    int lc_a = (tid & 3) * 8;          // 0/8/16/24
    int lr_w = tid >> 1;               // 0..127
    int lc_w = (tid & 1) * 16;         // 0/16

    const float* ga_base = A + (size_t)(mbase + lr_a) * CDIM + lc_a;
    const float* gw_base = W + (size_t)lr_w * CDIM + lc_w;

    float4 av[2], wv[4];
#pragma unroll
    for (int i = 0; i < 2; i++) av[i] = ((const float4*)ga_base)[i];
#pragma unroll
    for (int i = 0; i < 4; i++) wv[i] = ((const float4*)gw_base)[i];

    for (int k0 = 0; k0 < CDIM; k0 += 32) {
        if (k0) __syncthreads();               // prev compute done before overwrite
        uint2* sa = (uint2*)&As[lr_a * 40 + lc_a];
        uint2* sw = (uint2*)&Ws[lr_w * 40 + lc_w];
#pragma unroll
        for (int i = 0; i < 2; i++) {
            __nv_bfloat162 p0 = __floats2bfloat162_rn(av[i].x, av[i].y);
            __nv_bfloat162 p1 = __floats2bfloat162_rn(av[i].z, av[i].w);
            sa[i] = make_uint2(*(unsigned*)&p0, *(unsigned*)&p1);
        }
#pragma unroll
        for (int i = 0; i < 4; i++) {
            __nv_bfloat162 q0 = __floats2bfloat162_rn(wv[i].x, wv[i].y);
            __nv_bfloat162 q1 = __floats2bfloat162_rn(wv[i].z, wv[i].w);
            sw[i] = make_uint2(*(unsigned*)&q0, *(unsigned*)&q1);
        }
        __syncthreads();
        if (k0 + 32 < CDIM) {                  // prefetch next K-chunk
            const float4* ga = (const float4*)(ga_base + k0 + 32);
            const float4* gw = (const float4*)(gw_base + k0 + 32);
#pragma unroll
            for (int i = 0; i < 2; i++) av[i] = ga[i];
#pragma unroll
            for (int i = 0; i < 4; i++) wv[i] = gw[i];
        }
#pragma unroll
        for (int kk = 0; kk < 2; kk++) {
            unsigned af[2][4], bf2[4][2];
#pragma unroll
            for (int mt = 0; mt < 2; mt++)
                ldsm4(af[mt], as_u + (uint32_t)(((pm * 32 + mt * 16 + (lane & 15)) * 40 +
                                                 kk * 16 + (lane >> 4) * 8) * 2));
#pragma unroll
            for (int np = 0; np < 2; np++) {
                unsigned r4[4];
                ldsm4(r4, ws_u + (uint32_t)(((pn * 32 + np * 16 + (lane & 15)) * 40 +
                                             kk * 16 + (lane >> 4) * 8) * 2));
                bf2[np * 2][0] = r4[0]; bf2[np * 2][1] = r4[2];
                bf2[np * 2 + 1][0] = r4[1]; bf2[np * 2 + 1][1] = r4[3];
            }
#pragma unroll
            for (int mt = 0; mt < 2; mt++)
#pragma unroll
                for (int nt = 0; nt < 4; nt++)
                    mma_bf16(acc[mt][nt], af[mt], bf2[nt]);
        }
    }
#pragma unroll
    for (int mt = 0; mt < 2; mt++) {
        int r0 = mbase + pm * 32 + mt * 16 + (lane >> 2);
#pragma unroll
        for (int nt = 0; nt < 4; nt++) {
            int c0 = pn * 32 + nt * 8 + (lane & 3) * 2;
            __nv_bfloat162 v01 = __floats2bfloat162_rn(acc[mt][nt][0] * oscale,
                                                       acc[mt][nt][1] * oscale);
            __nv_bfloat162 v23 = __floats2bfloat162_rn(acc[mt][nt][2] * oscale,
                                                       acc[mt][nt][3] * oscale);
            *(__nv_bfloat162*)(&C[(size_t)r0 * DK + c0]) = v01;
            *(__nv_bfloat162*)(&C[(size_t)(r0 + 8) * DK + c0]) = v23;
        }
    }
}

// ---------------- 4) attention: num/den per query ----------------
__device__ __forceinline__ void load_kb(uint32_t ks_u, uint32_t vws_u, int tid, int buf, int krow0) {
    uint32_t kb = ks_u + (uint32_t)buf * (BN * QPITCH * 2);
#pragma unroll
    for (int p = 0; p < 8; p++) {
        int idx = p * 256 + tid;
        int r = idx >> 4, ch = idx & 15;
        cp16(kb + (uint32_t)((r * QPITCH + ch * 8) * 2),
             g_K + (size_t)(krow0 + r) * DK + ch * 8);
    }
    if (tid < 32)
        cp16(vws_u + (uint32_t)buf * BN * 4 + tid * 16, g_vw + krow0 + tid * 4);
}

extern __shared__ char smem_raw[];

__global__ void __launch_bounds__(256, 2) attn_kernel() {
    __nv_bfloat16* Qs = (__nv_bfloat16*)smem_raw;
    __nv_bfloat16* Ks = Qs + BM * QPITCH;
    float* vws   = (float*)(Ks + 2 * BN * QPITCH);
    float* num_s = vws + 2 * BN;
    float* den_s = num_s + BM;

    int tid = threadIdx.x, lane = tid & 31, wid = tid >> 5;
    int wm = wid >> 1, wn = wid & 1;            // warps 4(M) x 2(N), warp tile 32x64
    int qbase = blockIdx.x * BM;
    int split = blockIdx.y;
    int koff0 = split * (T_K / KSPLIT);

    uint32_t qs_u  = (uint32_t)__cvta_generic_to_shared(Qs);
    uint32_t ks_u  = (uint32_t)__cvta_generic_to_shared(Ks);
    uint32_t vws_u = (uint32_t)__cvta_generic_to_shared(vws);

#pragma unroll
    for (int p = 0; p < 8; p++) {               // Q tile, once
        int idx = p * 256 + tid;
        int r = idx >> 4, ch = idx & 15;
        cp16(qs_u + (uint32_t)((r * QPITCH + ch * 8) * 2),
             g_Q + (size_t)(qbase + r) * DK + ch * 8);
    }
    load_kb(ks_u, vws_u, tid, 0, koff0);
    asm volatile("cp.async.commit_group;");

    // hoisted ldsm base addresses (only kk / buffer offsets vary in-loop)
    uint32_t qa0 = qs_u + (uint32_t)(((wm * 32 + (lane & 15)) * QPITCH + (lane >> 4) * 8) * 2);
    uint32_t ka0 = ks_u + (uint32_t)(((wn * 64 + (lane & 15)) * QPITCH + (lane >> 4) * 8) * 2);
    const uint32_t TI_STEP = 16 * QPITCH * 2;
    const uint32_t BUF_STEP = BN * QPITCH * 2;

    float acc[2][8][4];
#pragma unroll
    for (int ti = 0; ti < 2; ti++)
#pragma unroll
        for (int tj = 0; tj < 8; tj++)
#pragma unroll
            for (int q = 0; q < 4; q++) acc[ti][tj][q] = 0.f;
    float num[2][2] = {{0.f, 0.f}, {0.f, 0.f}};
    float den[2][2] = {{0.f, 0.f}, {0.f, 0.f}};

    for (int kb = 0; kb < NKB; kb++) {
        if (kb + 1 < NKB) {
            load_kb(ks_u, vws_u, tid, (kb + 1) & 1, koff0 + (kb + 1) * BN);
            asm volatile("cp.async.commit_group;");
            asm volatile("cp.async.wait_group 1;");
        } else {
            asm volatile("cp.async.wait_group 0;");
        }
        __syncthreads();
        uint32_t kbuf = ka0 + (uint32_t)(kb & 1) * BUF_STEP;
#pragma unroll
        for (int kk = 0; kk < 8; kk++) {
            unsigned af[2][4];
#pragma unroll
            for (int ti = 0; ti < 2; ti++)
                ldsm4(af[ti], qa0 + (uint32_t)ti * TI_STEP + kk * 32);
            unsigned bf2[8][2];
#pragma unroll
            for (int tp = 0; tp < 4; tp++) {
                unsigned r4[4];
                ldsm4(r4, kbuf + (uint32_t)tp * TI_STEP + kk * 32);
                bf2[tp * 2][0] = r4[0]; bf2[tp * 2][1] = r4[2];
                bf2[tp * 2 + 1][0] = r4[1]; bf2[tp * 2 + 1][1] = r4[3];
            }
#pragma unroll
            for (int ti = 0; ti < 2; ti++)
#pragma unroll
                for (int tj = 0; tj < 8; tj++)
                    mma_bf16(acc[ti][tj], af[ti], bf2[tj]);
        }
        // exp + weighted accumulate (Q pre-scaled; scores tiny -> no max needed)
        const float* vb = vws + (kb & 1) * BN;
#pragma unroll
        for (int tj = 0; tj < 8; tj++) {
            int c0 = wn * 64 + tj * 8 + (lane & 3) * 2;
            float v0 = vb[c0], v1 = vb[c0 + 1];
#pragma unroll
            for (int ti = 0; ti < 2; ti++) {
                float e0 = ex2f(acc[ti][tj][0]);
                float e1 = ex2f(acc[ti][tj][1]);
                float e2 = ex2f(acc[ti][tj][2]);
                float e3 = ex2f(acc[ti][tj][3]);
                num[ti][0] += e0 * v0 + e1 * v1;
                den[ti][0] += e0 + e1;
                num[ti][1] += e2 * v0 + e3 * v1;
                den[ti][1] += e2 + e3;
                acc[ti][tj][0] = 0.f; acc[ti][tj][1] = 0.f;
                acc[ti][tj][2] = 0.f; acc[ti][tj][3] = 0.f;
            }
        }
        __syncthreads();   // all warps done with this buffer before it is refilled
    }

    // quad reduce across (lane&3): each quad covers distinct columns of same row
#pragma unroll
    for (int ti = 0; ti < 2; ti++)
#pragma unroll
        for (int h = 0; h < 2; h++) {
            num[ti][h] += __shfl_xor_sync(0xffffffffu, num[ti][h], 1);
            num[ti][h] += __shfl_xor_sync(0xffffffffu, num[ti][h], 2);
            den[ti][h] += __shfl_xor_sync(0xffffffffu, den[ti][h], 1);
            den[ti][h] += __shfl_xor_sync(0xffffffffu, den[ti][h], 2);
        }
    if ((lane & 3) == 0 && wn == 0) {
#pragma unroll
        for (int ti = 0; ti < 2; ti++)
#pragma unroll
            for (int h = 0; h < 2; h++) {
                int r = wm * 32 + ti * 16 + h * 8 + (lane >> 2);
                num_s[r] = num[ti][h]; den_s[r] = den[ti][h];
            }
    }
    __syncthreads();
    if ((lane & 3) == 0 && wn == 1) {
#pragma unroll
        for (int ti = 0; ti < 2; ti++)
#pragma unroll
            for (int h = 0; h < 2; h++) {
                int r = wm * 32 + ti * 16 + h * 8 + (lane >> 2);
                num_s[r] += num[ti][h]; den_s[r] += den[ti][h];
            }
    }
    __syncthreads();
    if (tid < BM) {
        g_pnum[split * S_Q + qbase + tid] = num_s[tid];
        g_pden[split * S_Q + qbase + tid] = den_s[tid];
    }
}

// ---------------- 5) gate: y = x1 * (1 - num/den)  (or x1 if sum(x2)==0) ----------------
__global__ void gate_kernel(const float* __restrict__ x1, float* __restrict__ y) {
    int row = blockIdx.x;
    float nu = 0.f, de = 0.f;
#pragma unroll
    for (int s = 0; s < KSPLIT; s++) {
        nu += g_pnum[s * S_Q + row];
        de += g_pden[s * S_Q + row];
    }
    float out = nu / de;
    float f = (g_sumx2 == 0.0f) ? 1.0f : (1.0f - out);
    int t = threadIdx.x;  // 192 threads * float4 = 768
    const float4* xr = (const float4*)(x1 + (size_t)row * CDIM);
    float4* yr = (float4*)(y + (size_t)row * CDIM);
    float4 v = xr[t];
    v.x *= f; v.y *= f; v.z *= f; v.w *= f;
    yr[t] = v;
}

// ---------------- launch ----------------
extern "C" void kernel_launch(void* const* d_in, const int* in_sizes, int n_in,
                              void* d_out, int out_size) {
    (void)in_sizes; (void)n_in; (void)out_size;
    const float* x1  = (const float*)d_in[0];
    const float* x2  = (const float*)d_in[1];
    const float* w_q = (const float*)d_in[2];
    const float* w_k = (const float*)d_in[3];
    const float* w_v = (const float*)d_in[4];
    const float* w_o = (const float*)d_in[5];
    float* y = (float*)d_out;

    cudaFuncSetAttribute(attn_kernel, cudaFuncAttributeMaxDynamicSharedMemorySize, ATTN_SMEM);

    prep_kernel<<<1, CDIM>>>(w_v, w_o);
    vw_kernel<<<T_K / 8, 256>>>(x2);
    proj2_kernel<<<dim3(S_Q / 64, 2), 256>>>(x1, x2, w_q, w_k);
    attn_kernel<<<dim3(S_Q / BM, KSPLIT), 256, ATTN_SMEM>>>();
    gate_kernel<<<S_Q, CDIM / 4>>>(x1, y);
}